// round 15
// baseline (speedup 1.0000x reference)
#include <cuda_runtime.h>
#include <cuda_fp16.h>
#include <cstdint>
#include <cstddef>

// Problem constants (fixed shapes from setup_inputs)
#define BATCH 2
#define SEQ   2048
#define CDIM  1024
#define NHEAD 16
#define HDIM  64
#define MROWS (BATCH * SEQ)          // 4096
#define QKVC  (3 * CDIM)             // 3072

// Scratch (allocation-free rule: __device__ globals)
__device__ __half g_x16[(size_t)MROWS * CDIM];       //  8 MB fp16 cast of x
__device__ __half g_qb[(size_t)MROWS * CDIM];        //  8 MB [b][h][t][d]
__device__ __half g_kb[(size_t)MROWS * CDIM];
__device__ __half g_vb[(size_t)MROWS * CDIM];
__device__ __half g_attn[(size_t)MROWS * CDIM];      //  8 MB attn output fp16
__device__ __half g_W1 [(size_t)QKVC * CDIM];        //  6 MB [N=3072][K=1024] Wqkv^T fp16
__device__ __half g_W2 [(size_t)CDIM * CDIM];        //  2 MB [N=1024][K=1024] Wout^T fp16

// ---------------------------------------------------------------------------
// Common PTX helpers
// ---------------------------------------------------------------------------
__device__ __forceinline__ uint32_t sw_off(int row, int col) {
    // XOR swizzle on 16B chunks within a 64-elt (128B) 16-bit row
    return (uint32_t)(row * 64 + ((((col >> 3) ^ (row & 7)) << 3) | (col & 7)));
}
__device__ __forceinline__ void ldm_x4(uint32_t& r0, uint32_t& r1,
                                       uint32_t& r2, uint32_t& r3, uint32_t a) {
    asm volatile("ldmatrix.sync.aligned.m8n8.x4.shared.b16 {%0,%1,%2,%3}, [%4];"
                 : "=r"(r0), "=r"(r1), "=r"(r2), "=r"(r3) : "r"(a));
}
__device__ __forceinline__ void ldm_x4_t(uint32_t& r0, uint32_t& r1,
                                         uint32_t& r2, uint32_t& r3, uint32_t a) {
    asm volatile("ldmatrix.sync.aligned.m8n8.x4.trans.shared.b16 {%0,%1,%2,%3}, [%4];"
                 : "=r"(r0), "=r"(r1), "=r"(r2), "=r"(r3) : "r"(a));
}
__device__ __forceinline__ void mma16816_f16(float* c, const uint32_t* a,
                                             uint32_t b0, uint32_t b1) {
    asm volatile(
        "mma.sync.aligned.m16n8k16.row.col.f32.f16.f16.f32 "
        "{%0,%1,%2,%3}, {%4,%5,%6,%7}, {%8,%9}, {%0,%1,%2,%3};"
        : "+f"(c[0]), "+f"(c[1]), "+f"(c[2]), "+f"(c[3])
        : "r"(a[0]), "r"(a[1]), "r"(a[2]), "r"(a[3]), "r"(b0), "r"(b1));
}
__device__ __forceinline__ float ex2f(float x) {
    float r;
    asm("ex2.approx.ftz.f32 %0, %1;" : "=f"(r) : "f"(x));
    return r;
}
__device__ __forceinline__ void cp16(uint32_t dst, const void* src) {
    asm volatile("cp.async.cg.shared.global [%0], [%1], 16;" :: "r"(dst), "l"(src));
}

// ---------------------------------------------------------------------------
// Fused prep: (a) x -> fp16 cast, (b) Wqkv transpose+cast, (c) Wout
// transpose+cast. 256 threads flat.
// ---------------------------------------------------------------------------
__device__ __forceinline__ void trans_tile(const float* __restrict__ W,
                                           __half* __restrict__ Wt,
                                           int K, int N, int bx, int by,
                                           int tx, int ty, float (*s)[33])
{
    const int k0 = by * 32, n0 = bx * 32;
    #pragma unroll
    for (int i = 0; i < 4; ++i)
        s[ty + i * 8][tx] = W[(size_t)(k0 + ty + i * 8) * N + n0 + tx];
    __syncthreads();
    #pragma unroll
    for (int i = 0; i < 4; ++i) {
        const int n = n0 + ty + i * 8, k = k0 + tx;
        Wt[(size_t)n * K + k] = __float2half_rn(s[tx][ty + i * 8]);
    }
}

#define PREP_CAST_BLKS  (MROWS * CDIM / 2 / 256)          // 8192
#define PREP_W1_BLKS    ((QKVC / 32) * (CDIM / 32))       // 3072
#define PREP_W2_BLKS    ((CDIM / 32) * (CDIM / 32))       // 1024

__global__ void prep_kernel(const float* __restrict__ x, __half* __restrict__ x16,
                            const float* __restrict__ Wqkv, __half* __restrict__ W1,
                            const float* __restrict__ Wout, __half* __restrict__ W2)
{
    __shared__ float s[32][33];
    const int bid = blockIdx.x;
    const int tid = threadIdx.x;
    if (bid < PREP_CAST_BLKS) {
        const int idx = bid * 256 + tid;
        const float2 v = *(const float2*)(x + (size_t)idx * 2);
        __half2 hh;
        hh.x = __float2half_rn(v.x);
        hh.y = __float2half_rn(v.y);
        *(__half2*)(x16 + (size_t)idx * 2) = hh;
    } else if (bid < PREP_CAST_BLKS + PREP_W1_BLKS) {
        const int j = bid - PREP_CAST_BLKS;
        trans_tile(Wqkv, W1, CDIM, QKVC, j % (QKVC / 32), j / (QKVC / 32),
                   tid & 31, tid >> 5, s);
    } else {
        const int j = bid - PREP_CAST_BLKS - PREP_W1_BLKS;
        trans_tile(Wout, W2, CDIM, CDIM, j % (CDIM / 32), j / (CDIM / 32),
                   tid & 31, tid >> 5, s);
    }
}

// ---------------------------------------------------------------------------
// Shared GEMM mainloop (128x64 tiles, 128 threads, 3-stage, frag ping-pong).
// ---------------------------------------------------------------------------
#define GM_BK 64
#define G1_NSTG 3
#define G1_STG_BYTES 24576   // 16 KB A + 8 KB B

extern __shared__ __half smem_dyn[];

__device__ __forceinline__ void gemm_n64_mainloop(
    const __half* __restrict__ A, const __half* __restrict__ Bt,
    int m0, int n0, int K, int tid, int lane, int wid,
    int wm, int wn, float acc[4][4][4])
{
    const int lrow = lane & 15, lcol8 = (lane >> 4) * 8;
    const uint32_t sBase = (uint32_t)__cvta_generic_to_shared(smem_dyn);

    const __half* Ag = A  + (size_t)m0 * K;
    const __half* Bg = Bt + (size_t)n0 * K;

    auto loadTile = [&](int it, int stg) {
        const __half* ag = Ag + it * GM_BK;
        const __half* bg = Bg + it * GM_BK;
        const uint32_t sa = sBase + stg * G1_STG_BYTES;
        const uint32_t sb = sa + 16384;
        #pragma unroll
        for (int e = tid; e < 1024; e += 128) {
            const int row = e >> 3, ch = e & 7;
            cp16(sa + 2 * sw_off(row, ch * 8), ag + (size_t)row * K + ch * 8);
        }
        #pragma unroll
        for (int e = tid; e < 512; e += 128) {
            const int row = e >> 3, ch = e & 7;
            cp16(sb + 2 * sw_off(row, ch * 8), bg + (size_t)row * K + ch * 8);
        }
        asm volatile("cp.async.commit_group;" ::: "memory");
    };

    const int kIters = K / GM_BK;
    loadTile(0, 0);
    loadTile(1, 1);

    uint32_t af[2][4][4];
    uint32_t bf[2][4][2];

    for (int it = 0; it < kIters; ++it) {
        asm volatile("cp.async.wait_group 1;" ::: "memory");
        __syncthreads();

        if (it + 2 < kIters) loadTile(it + 2, (it + 2) % G1_NSTG);
        else asm volatile("cp.async.commit_group;" ::: "memory");

        const uint32_t sa = sBase + (it % G1_NSTG) * G1_STG_BYTES;
        const uint32_t sb = sa + 16384;

        #pragma unroll
        for (int mt = 0; mt < 4; ++mt)
            ldm_x4(af[0][mt][0], af[0][mt][1], af[0][mt][2], af[0][mt][3],
                   sa + 2 * sw_off(wm + mt * 16 + lrow, lcol8));
        #pragma unroll
        for (int nt = 0; nt < 2; ++nt) {
            uint32_t r0, r1, r2, r3;
            ldm_x4(r0, r1, r2, r3, sb + 2 * sw_off(wn + nt * 16 + lrow, lcol8));
            bf[0][2 * nt][0] = r0;     bf[0][2 * nt][1] = r2;
            bf[0][2 * nt + 1][0] = r1; bf[0][2 * nt + 1][1] = r3;
        }

        #pragma unroll
        for (int k16 = 0; k16 < 4; ++k16) {
            const int cur = k16 & 1, nxt = cur ^ 1;
            if (k16 < 3) {
                #pragma unroll
                for (int mt = 0; mt < 4; ++mt)
                    ldm_x4(af[nxt][mt][0], af[nxt][mt][1],
                           af[nxt][mt][2], af[nxt][mt][3],
                           sa + 2 * sw_off(wm + mt * 16 + lrow,
                                           (k16 + 1) * 16 + lcol8));
                #pragma unroll
                for (int nt = 0; nt < 2; ++nt) {
                    uint32_t r0, r1, r2, r3;
                    ldm_x4(r0, r1, r2, r3,
                           sb + 2 * sw_off(wn + nt * 16 + lrow,
                                           (k16 + 1) * 16 + lcol8));
                    bf[nxt][2 * nt][0] = r0;     bf[nxt][2 * nt][1] = r2;
                    bf[nxt][2 * nt + 1][0] = r1; bf[nxt][2 * nt + 1][1] = r3;
                }
            }
            #pragma unroll
            for (int mt = 0; mt < 4; ++mt)
                #pragma unroll
                for (int nb = 0; nb < 4; ++nb)
                    mma16816_f16(acc[mt][nb], af[cur][mt],
                                 bf[cur][nb][0], bf[cur][nb][1]);
        }
    }
}

// ---------------------------------------------------------------------------
// GEMM1 + fused RoPE epilogue (mainloop shared; epilogue unchanged from R13).
// ---------------------------------------------------------------------------
__global__ __launch_bounds__(128, 3) void hgemm_rope_kernel(
    const __half* __restrict__ A,   // [M][K] = x16
    const __half* __restrict__ Bt,  // [N][K] = W1
    const float* __restrict__ bias, // bqkv
    __half* __restrict__ qb, __half* __restrict__ kb, __half* __restrict__ vb,
    int M, int N, int K)
{
    const int tid = threadIdx.x, lane = tid & 31, wid = tid >> 5;
    const int m0 = blockIdx.y * 128, n0 = blockIdx.x * 64;
    const int wm = (wid >> 1) * 64, wn = (wid & 1) * 32;

    float acc[4][4][4];
    #pragma unroll
    for (int mt = 0; mt < 4; ++mt)
        #pragma unroll
        for (int nb = 0; nb < 4; ++nb)
            #pragma unroll
            for (int r = 0; r < 4; ++r) acc[mt][nb][r] = 0.f;

    gemm_n64_mainloop(A, Bt, m0, n0, K, tid, lane, wid, wm, wn, acc);

    // ---- fused epilogue ----
    const int sec = n0 >> 10;               // 0=q, 1=k, 2=v
    const int h   = (n0 & 1023) >> 6;
    const int b   = m0 >> 11;
    const int t0  = m0 & (SEQ - 1);
    __half* outbase = (sec == 0 ? qb : (sec == 1 ? kb : vb))
                      + ((size_t)(b * NHEAD + h) * SEQ + t0) * HDIM;

    if (sec == 2) {
        #pragma unroll
        for (int mt = 0; mt < 4; ++mt) {
            const int r0 = wm + mt * 16 + (lane >> 2);
            #pragma unroll
            for (int nb = 0; nb < 4; ++nb) {
                const int cidx = wn + nb * 8 + (lane & 3) * 2;
                const float b0 = bias[n0 + cidx], b1 = bias[n0 + cidx + 1];
                *(__half2*)(outbase + (size_t)r0 * HDIM + cidx) =
                    __floats2half2_rn(acc[mt][nb][0] + b0, acc[mt][nb][1] + b1);
                *(__half2*)(outbase + (size_t)(r0 + 8) * HDIM + cidx) =
                    __floats2half2_rn(acc[mt][nb][2] + b0, acc[mt][nb][3] + b1);
            }
        }
        return;
    }

    float* st = (float*)smem_dyn;   // 128 x 64 fp32 = 32 KB
    __syncthreads();
    #pragma unroll
    for (int mt = 0; mt < 4; ++mt) {
        const int r0 = wm + mt * 16 + (lane >> 2);
        #pragma unroll
        for (int nb = 0; nb < 4; ++nb) {
            const int cidx = wn + nb * 8 + (lane & 3) * 2;
            const float b0 = bias[n0 + cidx], b1 = bias[n0 + cidx + 1];
            st[r0 * 64 + cidx]           = acc[mt][nb][0] + b0;
            st[r0 * 64 + cidx + 1]       = acc[mt][nb][1] + b1;
            st[(r0 + 8) * 64 + cidx]     = acc[mt][nb][2] + b0;
            st[(r0 + 8) * 64 + cidx + 1] = acc[mt][nb][3] + b1;
        }
    }
    __syncthreads();

    const float QS = (sec == 0) ? 0.125f * 1.4426950408889634f : 1.0f;
    #pragma unroll
    for (int i = 0; i < 16; ++i) {
        const int row = i * 8 + (tid >> 4);
        const int d   = (tid & 15) * 2;
        const float x1a = st[row * 64 + d];
        const float x1b = st[row * 64 + d + 1];
        const float x2a = st[row * 64 + d + 32];
        const float x2b = st[row * 64 + d + 33];

        const float tf = (float)(t0 + row);
        float sa, ca, sb_, cb;
        const float fa = exp2f((float)d       * (-13.2877123795494493f / 32.0f));
        const float fb = exp2f((float)(d + 1) * (-13.2877123795494493f / 32.0f));
        sincosf(tf * fa, &sa, &ca);
        sincosf(tf * fb, &sb_, &cb);

        const float o1a = (x1a * ca - x2a * sa) * QS;
        const float o1b = (x1b * cb - x2b * sb_) * QS;
        const float o2a = (x2a * ca + x1a * sa) * QS;
        const float o2b = (x2b * cb + x1b * sb_) * QS;

        *(__half2*)(outbase + (size_t)row * HDIM + d)      = __floats2half2_rn(o1a, o1b);
        *(__half2*)(outbase + (size_t)row * HDIM + d + 32) = __floats2half2_rn(o2a, o2b);
    }
}

// ---------------------------------------------------------------------------
// GEMM2: same 128x64 mainloop, fp32 + bias epilogue. 3 CTAs/SM, 512 CTAs.
// ---------------------------------------------------------------------------
__global__ __launch_bounds__(128, 3) void hgemm_f32_kernel(
    const __half* __restrict__ A,   // [M][K]
    const __half* __restrict__ Bt,  // [N][K]
    const float* __restrict__ bias, float* __restrict__ C,
    int M, int N, int K)
{
    const int tid = threadIdx.x, lane = tid & 31, wid = tid >> 5;
    const int m0 = blockIdx.y * 128, n0 = blockIdx.x * 64;
    const int wm = (wid >> 1) * 64, wn = (wid & 1) * 32;

    float acc[4][4][4];
    #pragma unroll
    for (int mt = 0; mt < 4; ++mt)
        #pragma unroll
        for (int nb = 0; nb < 4; ++nb)
            #pragma unroll
            for (int r = 0; r < 4; ++r) acc[mt][nb][r] = 0.f;

    gemm_n64_mainloop(A, Bt, m0, n0, K, tid, lane, wid, wm, wn, acc);

    #pragma unroll
    for (int mt = 0; mt < 4; ++mt) {
        const int r0 = m0 + wm + mt * 16 + (lane >> 2);
        #pragma unroll
        for (int nb = 0; nb < 4; ++nb) {
            const int cidx = n0 + wn + nb * 8 + (lane & 3) * 2;
            const float b0 = bias[cidx], b1 = bias[cidx + 1];
            *(float2*)(C + (size_t)r0 * N + cidx) =
                make_float2(acc[mt][nb][0] + b0, acc[mt][nb][1] + b1);
            *(float2*)(C + (size_t)(r0 + 8) * N + cidx) =
                make_float2(acc[mt][nb][2] + b0, acc[mt][nb][3] + b1);
        }
    }
}

// ---------------------------------------------------------------------------
// fp16 flash attention — FA_BM=64, 128 threads, 4 CTAs/SM (unchanged R14).
// ---------------------------------------------------------------------------
#define FA_BM 64
#define FA_BN 64
#define FA_TILES (SEQ / FA_BN)   // 32

__global__ __launch_bounds__(128, 4) void fa_kernel(
    const __half* __restrict__ Q, const __half* __restrict__ K,
    const __half* __restrict__ V, __half* __restrict__ attn)
{
    const int bh = blockIdx.y;
    const int b  = bh >> 4;
    const int h  = bh & 15;
    const int q0 = blockIdx.x * FA_BM;
    const int tid  = threadIdx.x;
    const int lane = tid & 31;
    const int wid  = tid >> 5;

    __shared__ __half sQ[FA_BM * HDIM];           // 8 KB
    __shared__ __half sK[2][FA_BN * HDIM];        // 16 KB
    __shared__ __half sV[2][FA_BN * HDIM];        // 16 KB

    const __half* qg = Q + ((size_t)bh * SEQ + q0) * HDIM;
    const __half* kg = K + (size_t)bh * SEQ * HDIM;
    const __half* vg = V + (size_t)bh * SEQ * HDIM;

    const uint32_t sQb  = (uint32_t)__cvta_generic_to_shared(sQ);
    const uint32_t sKb0 = (uint32_t)__cvta_generic_to_shared(sK[0]);
    const uint32_t sKb1 = (uint32_t)__cvta_generic_to_shared(sK[1]);
    const uint32_t sVb0 = (uint32_t)__cvta_generic_to_shared(sV[0]);
    const uint32_t sVb1 = (uint32_t)__cvta_generic_to_shared(sV[1]);

    #pragma unroll
    for (int e = tid; e < FA_BM * 8; e += 128) {
        const int row = e >> 3, ch = e & 7;
        *(uint4*)&sQ[sw_off(row, ch * 8)] = *(const uint4*)(qg + row * 64 + ch * 8);
    }

    #pragma unroll
    for (int pt = 0; pt < 2; ++pt) {
        const __half* kt = kg + pt * FA_BN * HDIM;
        const __half* vt = vg + pt * FA_BN * HDIM;
        const uint32_t kb = pt ? sKb1 : sKb0;
        const uint32_t vb = pt ? sVb1 : sVb0;
        #pragma unroll
        for (int e = tid; e < FA_BN * 8; e += 128) {
            const int row = e >> 3, ch = e & 7;
            const uint32_t so = 2 * sw_off(row, ch * 8);
            cp16(kb + so, kt + row * 64 + ch * 8);
            cp16(vb + so, vt + row * 64 + ch * 8);
        }
        asm volatile("cp.async.commit_group;" ::: "memory");
    }

    __syncthreads();

    uint32_t aq[4][4];
    {
        const int qr = wid * 16 + (lane & 15);
        const int qc = (lane >> 4) * 8;
        #pragma unroll
        for (int c4 = 0; c4 < 4; ++c4)
            ldm_x4(aq[c4][0], aq[c4][1], aq[c4][2], aq[c4][3],
                   sQb + 2 * sw_off(qr, c4 * 16 + qc));
    }

    float o[8][4];
    #pragma unroll
    for (int j = 0; j < 8; ++j)
        #pragma unroll
        for (int r = 0; r < 4; ++r) o[j][r] = 0.f;
    float m0 = -1e30f, m1 = -1e30f, l0 = 0.f, l1 = 0.f;

    const int lrow = lane & 15;
    const int lcol8 = (lane >> 4) * 8;

    for (int t = 0; t < FA_TILES; ++t) {
        if (t < FA_TILES - 1)
            asm volatile("cp.async.wait_group 1;" ::: "memory");
        else
            asm volatile("cp.async.wait_group 0;" ::: "memory");
        __syncthreads();

        const uint32_t kb = (t & 1) ? sKb1 : sKb0;
        const uint32_t vb = (t & 1) ? sVb1 : sVb0;

        float c[8][4];
        #pragma unroll
        for (int j = 0; j < 8; ++j)
            #pragma unroll
            for (int r = 0; r < 4; ++r) c[j][r] = 0.f;

        #pragma unroll
        for (int n16 = 0; n16 < 4; ++n16) {
            #pragma unroll
            for (int dc = 0; dc < 4; ++dc) {
                uint32_t r0, r1, r2, r3;
                ldm_x4(r0, r1, r2, r3,
                       kb + 2 * sw_off(n16 * 16 + lrow, dc * 16 + lcol8));
                mma16816_f16(c[2 * n16 + 0], aq[dc], r0, r2);
                mma16816_f16(c[2 * n16 + 1], aq[dc], r1, r3);
            }
        }

        float t0 = -1e30f, t1 = -1e30f;
        #pragma unroll
        for (int j = 0; j < 8; ++j) {
            t0 = fmaxf(t0, fmaxf(c[j][0], c[j][1]));
            t1 = fmaxf(t1, fmaxf(c[j][2], c[j][3]));
        }
        t0 = fmaxf(t0, __shfl_xor_sync(0xffffffffu, t0, 1));
        t0 = fmaxf(t0, __shfl_xor_sync(0xffffffffu, t0, 2));
        t1 = fmaxf(t1, __shfl_xor_sync(0xffffffffu, t1, 1));
        t1 = fmaxf(t1, __shfl_xor_sync(0xffffffffu, t1, 2));

        const float m0n = fmaxf(m0, t0);
        const float m1n = fmaxf(m1, t1);
        const float a0 = ex2f(m0 - m0n);
        const float a1 = ex2f(m1 - m1n);
        m0 = m0n; m1 = m1n;

        #pragma unroll
        for (int j = 0; j < 8; ++j) {
            o[j][0] *= a0; o[j][1] *= a0;
            o[j][2] *= a1; o[j][3] *= a1;
        }

        float s0 = 0.f, s1 = 0.f;
        #pragma unroll
        for (int kc = 0; kc < 4; ++kc) {
            uint32_t ap[4];
            #pragma unroll
            for (int jj = 0; jj < 2; ++jj) {
                const int j = 2 * kc + jj;
                const float p0 = ex2f(c[j][0] - m0);
                const float p1 = ex2f(c[j][1] - m0);
                const float p2 = ex2f(c[j][2] - m1);
                const float p3 = ex2f(c[j][3] - m1);
                s0 += p0 + p1;
                s1 += p2 + p3;
                __half2 u = __floats2half2_rn(p0, p1);
                __half2 w = __floats2half2_rn(p2, p3);
                ap[2 * jj + 0] = *(uint32_t*)&u;
                ap[2 * jj + 1] = *(uint32_t*)&w;
            }
            #pragma unroll
            for (int dc = 0; dc < 4; ++dc) {
                uint32_t r0, r1, r2, r3;
                ldm_x4_t(r0, r1, r2, r3,
                         vb + 2 * sw_off(kc * 16 + lrow, dc * 16 + lcol8));
                mma16816_f16(o[2 * dc + 0], ap, r0, r1);
                mma16816_f16(o[2 * dc + 1], ap, r2, r3);
            }
        }

        s0 += __shfl_xor_sync(0xffffffffu, s0, 1);
        s0 += __shfl_xor_sync(0xffffffffu, s0, 2);
        s1 += __shfl_xor_sync(0xffffffffu, s1, 1);
        s1 += __shfl_xor_sync(0xffffffffu, s1, 2);
        l0 = l0 * a0 + s0;
        l1 = l1 * a1 + s1;

        __syncthreads();

        if (t + 2 < FA_TILES) {
            const __half* kt = kg + (t + 2) * FA_BN * HDIM;
            const __half* vt = vg + (t + 2) * FA_BN * HDIM;
            const uint32_t kbn = (t & 1) ? sKb1 : sKb0;
            const uint32_t vbn = (t & 1) ? sVb1 : sVb0;
            #pragma unroll
            for (int e = tid; e < FA_BN * 8; e += 128) {
                const int row = e >> 3, ch = e & 7;
                const uint32_t so = 2 * sw_off(row, ch * 8);
                cp16(kbn + so, kt + row * 64 + ch * 8);
                cp16(vbn + so, vt + row * 64 + ch * 8);
            }
        }
        asm volatile("cp.async.commit_group;" ::: "memory");
    }

    const float inv0 = 1.0f / l0;
    const float inv1 = 1.0f / l1;
    const int g = lane >> 2;
    const int cq = (lane & 3) * 2;
    const int row0 = q0 + wid * 16 + g;
    const int row1 = row0 + 8;
    __half* ab0 = attn + (size_t)(b * SEQ + row0) * CDIM + h * HDIM + cq;
    __half* ab1 = attn + (size_t)(b * SEQ + row1) * CDIM + h * HDIM + cq;
    #pragma unroll
    for (int j = 0; j < 8; ++j) {
        *(__half2*)(ab0 + j * 8) = __floats2half2_rn(o[j][0] * inv0, o[j][1] * inv0);
        *(__half2*)(ab1 + j * 8) = __floats2half2_rn(o[j][2] * inv1, o[j][3] * inv1);
    }
}

// ---------------------------------------------------------------------------
// Launch
// ---------------------------------------------------------------------------
extern "C" void kernel_launch(void* const* d_in, const int* in_sizes, int n_in,
                              void* d_out, int out_size)
{
    const float* x    = (const float*)d_in[0];
    const float* Wqkv = (const float*)d_in[1];
    const float* bqkv = (const float*)d_in[2];
    const float* Wout = (const float*)d_in[3];
    const float* bout = (const float*)d_in[4];
    float* out = (float*)d_out;

    __half *x16 = nullptr, *qb = nullptr, *kb = nullptr, *vb = nullptr;
    __half *attn = nullptr, *W1 = nullptr, *W2 = nullptr;
    cudaGetSymbolAddress((void**)&x16, g_x16);
    cudaGetSymbolAddress((void**)&qb, g_qb);
    cudaGetSymbolAddress((void**)&kb, g_kb);
    cudaGetSymbolAddress((void**)&vb, g_vb);
    cudaGetSymbolAddress((void**)&attn, g_attn);
    cudaGetSymbolAddress((void**)&W1,  g_W1);
    cudaGetSymbolAddress((void**)&W2,  g_W2);

    const int G1_SMEM = G1_NSTG * G1_STG_BYTES;     // 73728
    cudaFuncSetAttribute(hgemm_rope_kernel,
                         cudaFuncAttributeMaxDynamicSharedMemorySize, G1_SMEM);
    cudaFuncSetAttribute(hgemm_f32_kernel,
                         cudaFuncAttributeMaxDynamicSharedMemorySize, G1_SMEM);

    // 1) fused prep: cast x -> x16, transpose Wqkv -> W1, Wout -> W2
    prep_kernel<<<PREP_CAST_BLKS + PREP_W1_BLKS + PREP_W2_BLKS, 256>>>(
        x, x16, Wqkv, W1, Wout, W2);

    // 2) qkv GEMM + fused RoPE + relayout -> qb/kb/vb directly
    hgemm_rope_kernel<<<dim3(QKVC / 64, MROWS / 128), 128, G1_SMEM>>>(
        x16, W1, bqkv, qb, kb, vb, MROWS, QKVC, CDIM);

    // 3) flash attention -> attn fp16
    fa_kernel<<<dim3(SEQ / FA_BM, BATCH * NHEAD), 128>>>(qb, kb, vb, attn);

    // 4) out = attn @ Wout + bout   (fine-grained tiles, 3 CTAs/SM)
    hgemm_f32_kernel<<<dim3(CDIM / 64, MROWS / 128), 128, G1_SMEM>>>(
        attn, W2, bout, out, MROWS, CDIM, CDIM);
}

// round 16
// speedup vs baseline: 1.0097x; 1.0097x over previous
#include <cuda_runtime.h>
#include <cuda_fp16.h>
#include <cstdint>
#include <cstddef>

// Problem constants (fixed shapes from setup_inputs)
#define BATCH 2
#define SEQ   2048
#define CDIM  1024
#define NHEAD 16
#define HDIM  64
#define MROWS (BATCH * SEQ)          // 4096
#define QKVC  (3 * CDIM)             // 3072

// Scratch (allocation-free rule: __device__ globals)
__device__ __half g_x16[(size_t)MROWS * CDIM];       //  8 MB fp16 cast of x
__device__ __half g_qb[(size_t)MROWS * CDIM];        //  8 MB [b][h][t][d]
__device__ __half g_kb[(size_t)MROWS * CDIM];
__device__ __half g_vb[(size_t)MROWS * CDIM];
__device__ __half g_attn[(size_t)MROWS * CDIM];      //  8 MB attn output fp16
__device__ __half g_W1 [(size_t)QKVC * CDIM];        //  6 MB [N=3072][K=1024] Wqkv^T fp16
__device__ __half g_W2 [(size_t)CDIM * CDIM];        //  2 MB [N=1024][K=1024] Wout^T fp16

// ---------------------------------------------------------------------------
// Common PTX helpers
// ---------------------------------------------------------------------------
__device__ __forceinline__ uint32_t sw_off(int row, int col) {
    // XOR swizzle on 16B chunks within a 64-elt (128B) 16-bit row
    return (uint32_t)(row * 64 + ((((col >> 3) ^ (row & 7)) << 3) | (col & 7)));
}
__device__ __forceinline__ void ldm_x4(uint32_t& r0, uint32_t& r1,
                                       uint32_t& r2, uint32_t& r3, uint32_t a) {
    asm volatile("ldmatrix.sync.aligned.m8n8.x4.shared.b16 {%0,%1,%2,%3}, [%4];"
                 : "=r"(r0), "=r"(r1), "=r"(r2), "=r"(r3) : "r"(a));
}
__device__ __forceinline__ void ldm_x4_t(uint32_t& r0, uint32_t& r1,
                                         uint32_t& r2, uint32_t& r3, uint32_t a) {
    asm volatile("ldmatrix.sync.aligned.m8n8.x4.trans.shared.b16 {%0,%1,%2,%3}, [%4];"
                 : "=r"(r0), "=r"(r1), "=r"(r2), "=r"(r3) : "r"(a));
}
__device__ __forceinline__ void mma16816_f16(float* c, const uint32_t* a,
                                             uint32_t b0, uint32_t b1) {
    asm volatile(
        "mma.sync.aligned.m16n8k16.row.col.f32.f16.f16.f32 "
        "{%0,%1,%2,%3}, {%4,%5,%6,%7}, {%8,%9}, {%0,%1,%2,%3};"
        : "+f"(c[0]), "+f"(c[1]), "+f"(c[2]), "+f"(c[3])
        : "r"(a[0]), "r"(a[1]), "r"(a[2]), "r"(a[3]), "r"(b0), "r"(b1));
}
__device__ __forceinline__ float ex2f(float x) {
    float r;
    asm("ex2.approx.ftz.f32 %0, %1;" : "=f"(r) : "f"(x));
    return r;
}
__device__ __forceinline__ void cp16(uint32_t dst, const void* src) {
    asm volatile("cp.async.cg.shared.global [%0], [%1], 16;" :: "r"(dst), "l"(src));
}

// ---------------------------------------------------------------------------
// Fused prep: (a) x -> fp16 cast, (b) Wqkv transpose+cast, (c) Wout
// transpose+cast. 256 threads flat.
// ---------------------------------------------------------------------------
__device__ __forceinline__ void trans_tile(const float* __restrict__ W,
                                           __half* __restrict__ Wt,
                                           int K, int N, int bx, int by,
                                           int tx, int ty, float (*s)[33])
{
    const int k0 = by * 32, n0 = bx * 32;
    #pragma unroll
    for (int i = 0; i < 4; ++i)
        s[ty + i * 8][tx] = W[(size_t)(k0 + ty + i * 8) * N + n0 + tx];
    __syncthreads();
    #pragma unroll
    for (int i = 0; i < 4; ++i) {
        const int n = n0 + ty + i * 8, k = k0 + tx;
        Wt[(size_t)n * K + k] = __float2half_rn(s[tx][ty + i * 8]);
    }
}

#define PREP_CAST_BLKS  (MROWS * CDIM / 2 / 256)          // 8192
#define PREP_W1_BLKS    ((QKVC / 32) * (CDIM / 32))       // 3072
#define PREP_W2_BLKS    ((CDIM / 32) * (CDIM / 32))       // 1024

__global__ void prep_kernel(const float* __restrict__ x, __half* __restrict__ x16,
                            const float* __restrict__ Wqkv, __half* __restrict__ W1,
                            const float* __restrict__ Wout, __half* __restrict__ W2)
{
    __shared__ float s[32][33];
    const int bid = blockIdx.x;
    const int tid = threadIdx.x;
    if (bid < PREP_CAST_BLKS) {
        const int idx = bid * 256 + tid;
        const float2 v = *(const float2*)(x + (size_t)idx * 2);
        __half2 hh;
        hh.x = __float2half_rn(v.x);
        hh.y = __float2half_rn(v.y);
        *(__half2*)(x16 + (size_t)idx * 2) = hh;
    } else if (bid < PREP_CAST_BLKS + PREP_W1_BLKS) {
        const int j = bid - PREP_CAST_BLKS;
        trans_tile(Wqkv, W1, CDIM, QKVC, j % (QKVC / 32), j / (QKVC / 32),
                   tid & 31, tid >> 5, s);
    } else {
        const int j = bid - PREP_CAST_BLKS - PREP_W1_BLKS;
        trans_tile(Wout, W2, CDIM, CDIM, j % (CDIM / 32), j / (CDIM / 32),
                   tid & 31, tid >> 5, s);
    }
}

// ---------------------------------------------------------------------------
// GEMM1 + fused RoPE epilogue (R13/R14 proven config).
// fp16 in, 128x64 tiles, 128 threads (4 warps, 2M x 2N, warp 64x32),
// 3-stage cp.async pipeline + register double-buffered fragments.
// ---------------------------------------------------------------------------
#define GM_BK 64
#define G1_NSTG 3
#define G1_STG_BYTES 24576   // 16 KB A + 8 KB B

extern __shared__ __half smem_dyn[];

__global__ __launch_bounds__(128, 3) void hgemm_rope_kernel(
    const __half* __restrict__ A,   // [M][K] = x16
    const __half* __restrict__ Bt,  // [N][K] = W1
    const float* __restrict__ bias, // bqkv
    __half* __restrict__ qb, __half* __restrict__ kb, __half* __restrict__ vb,
    int M, int N, int K)
{
    const int tid = threadIdx.x, lane = tid & 31, wid = tid >> 5;
    const int m0 = blockIdx.y * 128, n0 = blockIdx.x * 64;
    const int wm = (wid >> 1) * 64, wn = (wid & 1) * 32;
    const int lrow = lane & 15, lcol8 = (lane >> 4) * 8;

    const uint32_t sBase = (uint32_t)__cvta_generic_to_shared(smem_dyn);

    const __half* Ag = A  + (size_t)m0 * K;
    const __half* Bg = Bt + (size_t)n0 * K;

    auto loadTile = [&](int it, int stg) {
        const __half* ag = Ag + it * GM_BK;
        const __half* bg = Bg + it * GM_BK;
        const uint32_t sa = sBase + stg * G1_STG_BYTES;
        const uint32_t sb = sa + 16384;
        #pragma unroll
        for (int e = tid; e < 1024; e += 128) {
            const int row = e >> 3, ch = e & 7;
            cp16(sa + 2 * sw_off(row, ch * 8), ag + (size_t)row * K + ch * 8);
        }
        #pragma unroll
        for (int e = tid; e < 512; e += 128) {
            const int row = e >> 3, ch = e & 7;
            cp16(sb + 2 * sw_off(row, ch * 8), bg + (size_t)row * K + ch * 8);
        }
        asm volatile("cp.async.commit_group;" ::: "memory");
    };

    float acc[4][4][4];
    #pragma unroll
    for (int mt = 0; mt < 4; ++mt)
        #pragma unroll
        for (int nb = 0; nb < 4; ++nb)
            #pragma unroll
            for (int r = 0; r < 4; ++r) acc[mt][nb][r] = 0.f;

    const int kIters = K / GM_BK;
    loadTile(0, 0);
    loadTile(1, 1);

    uint32_t af[2][4][4];
    uint32_t bf[2][4][2];

    for (int it = 0; it < kIters; ++it) {
        asm volatile("cp.async.wait_group 1;" ::: "memory");
        __syncthreads();

        if (it + 2 < kIters) loadTile(it + 2, (it + 2) % G1_NSTG);
        else asm volatile("cp.async.commit_group;" ::: "memory");

        const uint32_t sa = sBase + (it % G1_NSTG) * G1_STG_BYTES;
        const uint32_t sb = sa + 16384;

        #pragma unroll
        for (int mt = 0; mt < 4; ++mt)
            ldm_x4(af[0][mt][0], af[0][mt][1], af[0][mt][2], af[0][mt][3],
                   sa + 2 * sw_off(wm + mt * 16 + lrow, lcol8));
        #pragma unroll
        for (int nt = 0; nt < 2; ++nt) {
            uint32_t r0, r1, r2, r3;
            ldm_x4(r0, r1, r2, r3, sb + 2 * sw_off(wn + nt * 16 + lrow, lcol8));
            bf[0][2 * nt][0] = r0;     bf[0][2 * nt][1] = r2;
            bf[0][2 * nt + 1][0] = r1; bf[0][2 * nt + 1][1] = r3;
        }

        #pragma unroll
        for (int k16 = 0; k16 < 4; ++k16) {
            const int cur = k16 & 1, nxt = cur ^ 1;
            if (k16 < 3) {
                #pragma unroll
                for (int mt = 0; mt < 4; ++mt)
                    ldm_x4(af[nxt][mt][0], af[nxt][mt][1],
                           af[nxt][mt][2], af[nxt][mt][3],
                           sa + 2 * sw_off(wm + mt * 16 + lrow,
                                           (k16 + 1) * 16 + lcol8));
                #pragma unroll
                for (int nt = 0; nt < 2; ++nt) {
                    uint32_t r0, r1, r2, r3;
                    ldm_x4(r0, r1, r2, r3,
                           sb + 2 * sw_off(wn + nt * 16 + lrow,
                                           (k16 + 1) * 16 + lcol8));
                    bf[nxt][2 * nt][0] = r0;     bf[nxt][2 * nt][1] = r2;
                    bf[nxt][2 * nt + 1][0] = r1; bf[nxt][2 * nt + 1][1] = r3;
                }
            }
            #pragma unroll
            for (int mt = 0; mt < 4; ++mt)
                #pragma unroll
                for (int nb = 0; nb < 4; ++nb)
                    mma16816_f16(acc[mt][nb], af[cur][mt],
                                 bf[cur][nb][0], bf[cur][nb][1]);
        }
    }

    // ---- fused epilogue ----
    const int sec = n0 >> 10;               // 0=q, 1=k, 2=v
    const int h   = (n0 & 1023) >> 6;
    const int b   = m0 >> 11;
    const int t0  = m0 & (SEQ - 1);
    __half* outbase = (sec == 0 ? qb : (sec == 1 ? kb : vb))
                      + ((size_t)(b * NHEAD + h) * SEQ + t0) * HDIM;

    if (sec == 2) {
        #pragma unroll
        for (int mt = 0; mt < 4; ++mt) {
            const int r0 = wm + mt * 16 + (lane >> 2);
            #pragma unroll
            for (int nb = 0; nb < 4; ++nb) {
                const int cidx = wn + nb * 8 + (lane & 3) * 2;
                const float b0 = bias[n0 + cidx], b1 = bias[n0 + cidx + 1];
                *(__half2*)(outbase + (size_t)r0 * HDIM + cidx) =
                    __floats2half2_rn(acc[mt][nb][0] + b0, acc[mt][nb][1] + b1);
                *(__half2*)(outbase + (size_t)(r0 + 8) * HDIM + cidx) =
                    __floats2half2_rn(acc[mt][nb][2] + b0, acc[mt][nb][3] + b1);
            }
        }
        return;
    }

    float* st = (float*)smem_dyn;   // 128 x 64 fp32 = 32 KB
    __syncthreads();
    #pragma unroll
    for (int mt = 0; mt < 4; ++mt) {
        const int r0 = wm + mt * 16 + (lane >> 2);
        #pragma unroll
        for (int nb = 0; nb < 4; ++nb) {
            const int cidx = wn + nb * 8 + (lane & 3) * 2;
            const float b0 = bias[n0 + cidx], b1 = bias[n0 + cidx + 1];
            st[r0 * 64 + cidx]           = acc[mt][nb][0] + b0;
            st[r0 * 64 + cidx + 1]       = acc[mt][nb][1] + b1;
            st[(r0 + 8) * 64 + cidx]     = acc[mt][nb][2] + b0;
            st[(r0 + 8) * 64 + cidx + 1] = acc[mt][nb][3] + b1;
        }
    }
    __syncthreads();

    const float QS = (sec == 0) ? 0.125f * 1.4426950408889634f : 1.0f;
    #pragma unroll
    for (int i = 0; i < 16; ++i) {
        const int row = i * 8 + (tid >> 4);
        const int d   = (tid & 15) * 2;
        const float x1a = st[row * 64 + d];
        const float x1b = st[row * 64 + d + 1];
        const float x2a = st[row * 64 + d + 32];
        const float x2b = st[row * 64 + d + 33];

        const float tf = (float)(t0 + row);
        float sa, ca, sb_, cb;
        const float fa = exp2f((float)d       * (-13.2877123795494493f / 32.0f));
        const float fb = exp2f((float)(d + 1) * (-13.2877123795494493f / 32.0f));
        sincosf(tf * fa, &sa, &ca);
        sincosf(tf * fb, &sb_, &cb);

        const float o1a = (x1a * ca - x2a * sa) * QS;
        const float o1b = (x1b * cb - x2b * sb_) * QS;
        const float o2a = (x2a * ca + x1a * sa) * QS;
        const float o2b = (x2b * cb + x1b * sb_) * QS;

        *(__half2*)(outbase + (size_t)row * HDIM + d)      = __floats2half2_rn(o1a, o1b);
        *(__half2*)(outbase + (size_t)row * HDIM + d + 32) = __floats2half2_rn(o2a, o2b);
    }
}

// ---------------------------------------------------------------------------
// GEMM2 (reverted to R14 best): fp16 in, fp32 out, 128x128x64, 3-stage,
// 256 threads, 2 CTAs/SM. Measured 32.4 us.
// ---------------------------------------------------------------------------
#define GM_NSTG 3
#define GM_STG_BYTES 32768   // 16KB A + 16KB B

__global__ __launch_bounds__(256) void hgemm_bias_kernel(
    const __half* __restrict__ A,   // [M][K]
    const __half* __restrict__ Bt,  // [N][K]
    const float* __restrict__ bias, float* __restrict__ C,
    int M, int N, int K)
{
    const int tid = threadIdx.x, lane = tid & 31, wid = tid >> 5;
    const int m0 = blockIdx.y * 128, n0 = blockIdx.x * 128;
    const int wm = (wid >> 2) * 64, wn = (wid & 3) * 32;
    const int lrow = lane & 15, lcol8 = (lane >> 4) * 8;

    const uint32_t sBase = (uint32_t)__cvta_generic_to_shared(smem_dyn);

    const __half* Ag = A  + (size_t)m0 * K;
    const __half* Bg = Bt + (size_t)n0 * K;

    auto loadTile = [&](int it, int stg) {
        const __half* ag = Ag + it * GM_BK;
        const __half* bg = Bg + it * GM_BK;
        const uint32_t sa = sBase + stg * GM_STG_BYTES;
        const uint32_t sb = sa + 16384;
        #pragma unroll
        for (int e = tid; e < 1024; e += 256) {
            const int row = e >> 3, ch = e & 7;
            const uint32_t so = 2 * sw_off(row, ch * 8);
            cp16(sa + so, ag + (size_t)row * K + ch * 8);
            cp16(sb + so, bg + (size_t)row * K + ch * 8);
        }
        asm volatile("cp.async.commit_group;" ::: "memory");
    };

    float acc[4][4][4];
    #pragma unroll
    for (int mt = 0; mt < 4; ++mt)
        #pragma unroll
        for (int nb = 0; nb < 4; ++nb)
            #pragma unroll
            for (int r = 0; r < 4; ++r) acc[mt][nb][r] = 0.f;

    const int kIters = K / GM_BK;
    loadTile(0, 0);
    loadTile(1, 1);

    for (int it = 0; it < kIters; ++it) {
        asm volatile("cp.async.wait_group 1;" ::: "memory");
        __syncthreads();

        if (it + 2 < kIters) loadTile(it + 2, (it + 2) % GM_NSTG);
        else asm volatile("cp.async.commit_group;" ::: "memory");

        const uint32_t sa = sBase + (it % GM_NSTG) * GM_STG_BYTES;
        const uint32_t sb = sa + 16384;

        #pragma unroll
        for (int k16 = 0; k16 < 4; ++k16) {
            uint32_t af[4][4];
            #pragma unroll
            for (int mt = 0; mt < 4; ++mt)
                ldm_x4(af[mt][0], af[mt][1], af[mt][2], af[mt][3],
                       sa + 2 * sw_off(wm + mt * 16 + lrow, k16 * 16 + lcol8));
            uint32_t bfr[4][2];
            #pragma unroll
            for (int nt = 0; nt < 2; ++nt) {
                uint32_t r0, r1, r2, r3;
                ldm_x4(r0, r1, r2, r3,
                       sb + 2 * sw_off(wn + nt * 16 + lrow, k16 * 16 + lcol8));
                bfr[2 * nt][0] = r0; bfr[2 * nt][1] = r2;
                bfr[2 * nt + 1][0] = r1; bfr[2 * nt + 1][1] = r3;
            }
            #pragma unroll
            for (int mt = 0; mt < 4; ++mt)
                #pragma unroll
                for (int nb = 0; nb < 4; ++nb)
                    mma16816_f16(acc[mt][nb], af[mt], bfr[nb][0], bfr[nb][1]);
        }
    }

    #pragma unroll
    for (int mt = 0; mt < 4; ++mt) {
        const int r0 = m0 + wm + mt * 16 + (lane >> 2);
        #pragma unroll
        for (int nb = 0; nb < 4; ++nb) {
            const int cidx = n0 + wn + nb * 8 + (lane & 3) * 2;
            const float b0 = bias[cidx], b1 = bias[cidx + 1];
            *(float2*)(C + (size_t)r0 * N + cidx) =
                make_float2(acc[mt][nb][0] + b0, acc[mt][nb][1] + b1);
            *(float2*)(C + (size_t)(r0 + 8) * N + cidx) =
                make_float2(acc[mt][nb][2] + b0, acc[mt][nb][3] + b1);
        }
    }
}

// ---------------------------------------------------------------------------
// fp16 flash attention — FA_BM=64, 128 threads, 4 CTAs/SM (unchanged R14).
// ---------------------------------------------------------------------------
#define FA_BM 64
#define FA_BN 64
#define FA_TILES (SEQ / FA_BN)   // 32

__global__ __launch_bounds__(128, 4) void fa_kernel(
    const __half* __restrict__ Q, const __half* __restrict__ K,
    const __half* __restrict__ V, __half* __restrict__ attn)
{
    const int bh = blockIdx.y;
    const int b  = bh >> 4;
    const int h  = bh & 15;
    const int q0 = blockIdx.x * FA_BM;
    const int tid  = threadIdx.x;
    const int lane = tid & 31;
    const int wid  = tid >> 5;

    __shared__ __half sQ[FA_BM * HDIM];           // 8 KB
    __shared__ __half sK[2][FA_BN * HDIM];        // 16 KB
    __shared__ __half sV[2][FA_BN * HDIM];        // 16 KB

    const __half* qg = Q + ((size_t)bh * SEQ + q0) * HDIM;
    const __half* kg = K + (size_t)bh * SEQ * HDIM;
    const __half* vg = V + (size_t)bh * SEQ * HDIM;

    const uint32_t sQb  = (uint32_t)__cvta_generic_to_shared(sQ);
    const uint32_t sKb0 = (uint32_t)__cvta_generic_to_shared(sK[0]);
    const uint32_t sKb1 = (uint32_t)__cvta_generic_to_shared(sK[1]);
    const uint32_t sVb0 = (uint32_t)__cvta_generic_to_shared(sV[0]);
    const uint32_t sVb1 = (uint32_t)__cvta_generic_to_shared(sV[1]);

    #pragma unroll
    for (int e = tid; e < FA_BM * 8; e += 128) {
        const int row = e >> 3, ch = e & 7;
        *(uint4*)&sQ[sw_off(row, ch * 8)] = *(const uint4*)(qg + row * 64 + ch * 8);
    }

    #pragma unroll
    for (int pt = 0; pt < 2; ++pt) {
        const __half* kt = kg + pt * FA_BN * HDIM;
        const __half* vt = vg + pt * FA_BN * HDIM;
        const uint32_t kb = pt ? sKb1 : sKb0;
        const uint32_t vb = pt ? sVb1 : sVb0;
        #pragma unroll
        for (int e = tid; e < FA_BN * 8; e += 128) {
            const int row = e >> 3, ch = e & 7;
            const uint32_t so = 2 * sw_off(row, ch * 8);
            cp16(kb + so, kt + row * 64 + ch * 8);
            cp16(vb + so, vt + row * 64 + ch * 8);
        }
        asm volatile("cp.async.commit_group;" ::: "memory");
    }

    __syncthreads();

    uint32_t aq[4][4];
    {
        const int qr = wid * 16 + (lane & 15);
        const int qc = (lane >> 4) * 8;
        #pragma unroll
        for (int c4 = 0; c4 < 4; ++c4)
            ldm_x4(aq[c4][0], aq[c4][1], aq[c4][2], aq[c4][3],
                   sQb + 2 * sw_off(qr, c4 * 16 + qc));
    }

    float o[8][4];
    #pragma unroll
    for (int j = 0; j < 8; ++j)
        #pragma unroll
        for (int r = 0; r < 4; ++r) o[j][r] = 0.f;
    float m0 = -1e30f, m1 = -1e30f, l0 = 0.f, l1 = 0.f;

    const int lrow = lane & 15;
    const int lcol8 = (lane >> 4) * 8;

    for (int t = 0; t < FA_TILES; ++t) {
        if (t < FA_TILES - 1)
            asm volatile("cp.async.wait_group 1;" ::: "memory");
        else
            asm volatile("cp.async.wait_group 0;" ::: "memory");
        __syncthreads();

        const uint32_t kb = (t & 1) ? sKb1 : sKb0;
        const uint32_t vb = (t & 1) ? sVb1 : sVb0;

        float c[8][4];
        #pragma unroll
        for (int j = 0; j < 8; ++j)
            #pragma unroll
            for (int r = 0; r < 4; ++r) c[j][r] = 0.f;

        #pragma unroll
        for (int n16 = 0; n16 < 4; ++n16) {
            #pragma unroll
            for (int dc = 0; dc < 4; ++dc) {
                uint32_t r0, r1, r2, r3;
                ldm_x4(r0, r1, r2, r3,
                       kb + 2 * sw_off(n16 * 16 + lrow, dc * 16 + lcol8));
                mma16816_f16(c[2 * n16 + 0], aq[dc], r0, r2);
                mma16816_f16(c[2 * n16 + 1], aq[dc], r1, r3);
            }
        }

        float t0 = -1e30f, t1 = -1e30f;
        #pragma unroll
        for (int j = 0; j < 8; ++j) {
            t0 = fmaxf(t0, fmaxf(c[j][0], c[j][1]));
            t1 = fmaxf(t1, fmaxf(c[j][2], c[j][3]));
        }
        t0 = fmaxf(t0, __shfl_xor_sync(0xffffffffu, t0, 1));
        t0 = fmaxf(t0, __shfl_xor_sync(0xffffffffu, t0, 2));
        t1 = fmaxf(t1, __shfl_xor_sync(0xffffffffu, t1, 1));
        t1 = fmaxf(t1, __shfl_xor_sync(0xffffffffu, t1, 2));

        const float m0n = fmaxf(m0, t0);
        const float m1n = fmaxf(m1, t1);
        const float a0 = ex2f(m0 - m0n);
        const float a1 = ex2f(m1 - m1n);
        m0 = m0n; m1 = m1n;

        #pragma unroll
        for (int j = 0; j < 8; ++j) {
            o[j][0] *= a0; o[j][1] *= a0;
            o[j][2] *= a1; o[j][3] *= a1;
        }

        float s0 = 0.f, s1 = 0.f;
        #pragma unroll
        for (int kc = 0; kc < 4; ++kc) {
            uint32_t ap[4];
            #pragma unroll
            for (int jj = 0; jj < 2; ++jj) {
                const int j = 2 * kc + jj;
                const float p0 = ex2f(c[j][0] - m0);
                const float p1 = ex2f(c[j][1] - m0);
                const float p2 = ex2f(c[j][2] - m1);
                const float p3 = ex2f(c[j][3] - m1);
                s0 += p0 + p1;
                s1 += p2 + p3;
                __half2 u = __floats2half2_rn(p0, p1);
                __half2 w = __floats2half2_rn(p2, p3);
                ap[2 * jj + 0] = *(uint32_t*)&u;
                ap[2 * jj + 1] = *(uint32_t*)&w;
            }
            #pragma unroll
            for (int dc = 0; dc < 4; ++dc) {
                uint32_t r0, r1, r2, r3;
                ldm_x4_t(r0, r1, r2, r3,
                         vb + 2 * sw_off(kc * 16 + lrow, dc * 16 + lcol8));
                mma16816_f16(o[2 * dc + 0], ap, r0, r1);
                mma16816_f16(o[2 * dc + 1], ap, r2, r3);
            }
        }

        s0 += __shfl_xor_sync(0xffffffffu, s0, 1);
        s0 += __shfl_xor_sync(0xffffffffu, s0, 2);
        s1 += __shfl_xor_sync(0xffffffffu, s1, 1);
        s1 += __shfl_xor_sync(0xffffffffu, s1, 2);
        l0 = l0 * a0 + s0;
        l1 = l1 * a1 + s1;

        __syncthreads();

        if (t + 2 < FA_TILES) {
            const __half* kt = kg + (t + 2) * FA_BN * HDIM;
            const __half* vt = vg + (t + 2) * FA_BN * HDIM;
            const uint32_t kbn = (t & 1) ? sKb1 : sKb0;
            const uint32_t vbn = (t & 1) ? sVb1 : sVb0;
            #pragma unroll
            for (int e = tid; e < FA_BN * 8; e += 128) {
                const int row = e >> 3, ch = e & 7;
                const uint32_t so = 2 * sw_off(row, ch * 8);
                cp16(kbn + so, kt + row * 64 + ch * 8);
                cp16(vbn + so, vt + row * 64 + ch * 8);
            }
        }
        asm volatile("cp.async.commit_group;" ::: "memory");
    }

    const float inv0 = 1.0f / l0;
    const float inv1 = 1.0f / l1;
    const int g = lane >> 2;
    const int cq = (lane & 3) * 2;
    const int row0 = q0 + wid * 16 + g;
    const int row1 = row0 + 8;
    __half* ab0 = attn + (size_t)(b * SEQ + row0) * CDIM + h * HDIM + cq;
    __half* ab1 = attn + (size_t)(b * SEQ + row1) * CDIM + h * HDIM + cq;
    #pragma unroll
    for (int j = 0; j < 8; ++j) {
        *(__half2*)(ab0 + j * 8) = __floats2half2_rn(o[j][0] * inv0, o[j][1] * inv0);
        *(__half2*)(ab1 + j * 8) = __floats2half2_rn(o[j][2] * inv1, o[j][3] * inv1);
    }
}

// ---------------------------------------------------------------------------
// Launch
// ---------------------------------------------------------------------------
extern "C" void kernel_launch(void* const* d_in, const int* in_sizes, int n_in,
                              void* d_out, int out_size)
{
    const float* x    = (const float*)d_in[0];
    const float* Wqkv = (const float*)d_in[1];
    const float* bqkv = (const float*)d_in[2];
    const float* Wout = (const float*)d_in[3];
    const float* bout = (const float*)d_in[4];
    float* out = (float*)d_out;

    __half *x16 = nullptr, *qb = nullptr, *kb = nullptr, *vb = nullptr;
    __half *attn = nullptr, *W1 = nullptr, *W2 = nullptr;
    cudaGetSymbolAddress((void**)&x16, g_x16);
    cudaGetSymbolAddress((void**)&qb, g_qb);
    cudaGetSymbolAddress((void**)&kb, g_kb);
    cudaGetSymbolAddress((void**)&vb, g_vb);
    cudaGetSymbolAddress((void**)&attn, g_attn);
    cudaGetSymbolAddress((void**)&W1,  g_W1);
    cudaGetSymbolAddress((void**)&W2,  g_W2);

    const int G1_SMEM = G1_NSTG * G1_STG_BYTES;     // 73728
    const int G2_SMEM = GM_NSTG * GM_STG_BYTES;     // 98304
    cudaFuncSetAttribute(hgemm_rope_kernel,
                         cudaFuncAttributeMaxDynamicSharedMemorySize, G1_SMEM);
    cudaFuncSetAttribute(hgemm_bias_kernel,
                         cudaFuncAttributeMaxDynamicSharedMemorySize, G2_SMEM);

    // 1) fused prep: cast x -> x16, transpose Wqkv -> W1, Wout -> W2
    prep_kernel<<<PREP_CAST_BLKS + PREP_W1_BLKS + PREP_W2_BLKS, 256>>>(
        x, x16, Wqkv, W1, Wout, W2);

    // 2) qkv GEMM + fused RoPE + relayout -> qb/kb/vb directly
    hgemm_rope_kernel<<<dim3(QKVC / 64, MROWS / 128), 128, G1_SMEM>>>(
        x16, W1, bqkv, qb, kb, vb, MROWS, QKVC, CDIM);

    // 3) flash attention -> attn fp16
    fa_kernel<<<dim3(SEQ / FA_BM, BATCH * NHEAD), 128>>>(qb, kb, vb, attn);

    // 4) out = attn @ Wout + bout   (R14 proven 256-thread 128x128 config)
    hgemm_bias_kernel<<<dim3(CDIM / 128, MROWS / 128), 256, G2_SMEM>>>(
        attn, W2, bout, out, MROWS, CDIM, CDIM);
}

// round 17
// speedup vs baseline: 1.0346x; 1.0247x over previous
#include <cuda_runtime.h>
#include <cuda_fp16.h>
#include <cstdint>
#include <cstddef>

// Problem constants (fixed shapes from setup_inputs)
#define BATCH 2
#define SEQ   2048
#define CDIM  1024
#define NHEAD 16
#define HDIM  64
#define MROWS (BATCH * SEQ)          // 4096
#define QKVC  (3 * CDIM)             // 3072

// Scratch (allocation-free rule: __device__ globals)
__device__ __half g_x16[(size_t)MROWS * CDIM];       //  8 MB fp16 cast of x
__device__ __half g_qb[(size_t)MROWS * CDIM];        //  8 MB [b][h][t][d]
__device__ __half g_kb[(size_t)MROWS * CDIM];
__device__ __half g_vb[(size_t)MROWS * CDIM];
__device__ __half g_attn[(size_t)MROWS * CDIM];      //  8 MB attn output fp16
__device__ __half g_W1 [(size_t)QKVC * CDIM];        //  6 MB [N=3072][K=1024] Wqkv^T fp16
__device__ __half g_W2 [(size_t)CDIM * CDIM];        //  2 MB [N=1024][K=1024] Wout^T fp16

// ---------------------------------------------------------------------------
// Common PTX helpers
// ---------------------------------------------------------------------------
__device__ __forceinline__ uint32_t sw_off(int row, int col) {
    // XOR swizzle on 16B chunks within a 64-elt (128B) 16-bit row
    return (uint32_t)(row * 64 + ((((col >> 3) ^ (row & 7)) << 3) | (col & 7)));
}
__device__ __forceinline__ void ldm_x4(uint32_t& r0, uint32_t& r1,
                                       uint32_t& r2, uint32_t& r3, uint32_t a) {
    asm volatile("ldmatrix.sync.aligned.m8n8.x4.shared.b16 {%0,%1,%2,%3}, [%4];"
                 : "=r"(r0), "=r"(r1), "=r"(r2), "=r"(r3) : "r"(a));
}
__device__ __forceinline__ void ldm_x4_t(uint32_t& r0, uint32_t& r1,
                                         uint32_t& r2, uint32_t& r3, uint32_t a) {
    asm volatile("ldmatrix.sync.aligned.m8n8.x4.trans.shared.b16 {%0,%1,%2,%3}, [%4];"
                 : "=r"(r0), "=r"(r1), "=r"(r2), "=r"(r3) : "r"(a));
}
__device__ __forceinline__ void mma16816_f16(float* c, const uint32_t* a,
                                             uint32_t b0, uint32_t b1) {
    asm volatile(
        "mma.sync.aligned.m16n8k16.row.col.f32.f16.f16.f32 "
        "{%0,%1,%2,%3}, {%4,%5,%6,%7}, {%8,%9}, {%0,%1,%2,%3};"
        : "+f"(c[0]), "+f"(c[1]), "+f"(c[2]), "+f"(c[3])
        : "r"(a[0]), "r"(a[1]), "r"(a[2]), "r"(a[3]), "r"(b0), "r"(b1));
}
__device__ __forceinline__ float ex2f(float x) {
    float r;
    asm("ex2.approx.ftz.f32 %0, %1;" : "=f"(r) : "f"(x));
    return r;
}
__device__ __forceinline__ void cp16(uint32_t dst, const void* src) {
    asm volatile("cp.async.cg.shared.global [%0], [%1], 16;" :: "r"(dst), "l"(src));
}

// ---------------------------------------------------------------------------
// Fused prep: (a) x -> fp16 cast, (b) Wqkv transpose+cast, (c) Wout
// transpose+cast. 256 threads flat.
// ---------------------------------------------------------------------------
__device__ __forceinline__ void trans_tile(const float* __restrict__ W,
                                           __half* __restrict__ Wt,
                                           int K, int N, int bx, int by,
                                           int tx, int ty, float (*s)[33])
{
    const int k0 = by * 32, n0 = bx * 32;
    #pragma unroll
    for (int i = 0; i < 4; ++i)
        s[ty + i * 8][tx] = W[(size_t)(k0 + ty + i * 8) * N + n0 + tx];
    __syncthreads();
    #pragma unroll
    for (int i = 0; i < 4; ++i) {
        const int n = n0 + ty + i * 8, k = k0 + tx;
        Wt[(size_t)n * K + k] = __float2half_rn(s[tx][ty + i * 8]);
    }
}

#define PREP_CAST_BLKS  (MROWS * CDIM / 2 / 256)          // 8192
#define PREP_W1_BLKS    ((QKVC / 32) * (CDIM / 32))       // 3072
#define PREP_W2_BLKS    ((CDIM / 32) * (CDIM / 32))       // 1024

__global__ void prep_kernel(const float* __restrict__ x, __half* __restrict__ x16,
                            const float* __restrict__ Wqkv, __half* __restrict__ W1,
                            const float* __restrict__ Wout, __half* __restrict__ W2)
{
    __shared__ float s[32][33];
    const int bid = blockIdx.x;
    const int tid = threadIdx.x;
    if (bid < PREP_CAST_BLKS) {
        const int idx = bid * 256 + tid;
        const float2 v = *(const float2*)(x + (size_t)idx * 2);
        __half2 hh;
        hh.x = __float2half_rn(v.x);
        hh.y = __float2half_rn(v.y);
        *(__half2*)(x16 + (size_t)idx * 2) = hh;
    } else if (bid < PREP_CAST_BLKS + PREP_W1_BLKS) {
        const int j = bid - PREP_CAST_BLKS;
        trans_tile(Wqkv, W1, CDIM, QKVC, j % (QKVC / 32), j / (QKVC / 32),
                   tid & 31, tid >> 5, s);
    } else {
        const int j = bid - PREP_CAST_BLKS - PREP_W1_BLKS;
        trans_tile(Wout, W2, CDIM, CDIM, j % (CDIM / 32), j / (CDIM / 32),
                   tid & 31, tid >> 5, s);
    }
}

// ---------------------------------------------------------------------------
// GEMM1 + fused RoPE epilogue — 2-stage pipeline, 4 CTAs/SM experiment.
// fp16 in, 128x64 tiles, 128 threads (4 warps, 2M x 2N, warp 64x32).
// Straight per-k16 ldmatrix (no frag ping-pong) to fit 128 regs.
// ---------------------------------------------------------------------------
#define GM_BK 64
#define G1_NSTG 2
#define G1_STG_BYTES 24576   // 16 KB A + 8 KB B

extern __shared__ __half smem_dyn[];

__global__ __launch_bounds__(128, 4) void hgemm_rope_kernel(
    const __half* __restrict__ A,   // [M][K] = x16
    const __half* __restrict__ Bt,  // [N][K] = W1
    const float* __restrict__ bias, // bqkv
    __half* __restrict__ qb, __half* __restrict__ kb, __half* __restrict__ vb,
    int M, int N, int K)
{
    const int tid = threadIdx.x, lane = tid & 31, wid = tid >> 5;
    const int m0 = blockIdx.y * 128, n0 = blockIdx.x * 64;
    const int wm = (wid >> 1) * 64, wn = (wid & 1) * 32;
    const int lrow = lane & 15, lcol8 = (lane >> 4) * 8;

    const uint32_t sBase = (uint32_t)__cvta_generic_to_shared(smem_dyn);

    const __half* Ag = A  + (size_t)m0 * K;
    const __half* Bg = Bt + (size_t)n0 * K;

    auto loadTile = [&](int it, int stg) {
        const __half* ag = Ag + it * GM_BK;
        const __half* bg = Bg + it * GM_BK;
        const uint32_t sa = sBase + stg * G1_STG_BYTES;
        const uint32_t sb = sa + 16384;
        #pragma unroll
        for (int e = tid; e < 1024; e += 128) {         // A: 128 rows x 8 chunks
            const int row = e >> 3, ch = e & 7;
            cp16(sa + 2 * sw_off(row, ch * 8), ag + (size_t)row * K + ch * 8);
        }
        #pragma unroll
        for (int e = tid; e < 512; e += 128) {          // B: 64 rows x 8 chunks
            const int row = e >> 3, ch = e & 7;
            cp16(sb + 2 * sw_off(row, ch * 8), bg + (size_t)row * K + ch * 8);
        }
        asm volatile("cp.async.commit_group;" ::: "memory");
    };

    float acc[4][4][4];
    #pragma unroll
    for (int mt = 0; mt < 4; ++mt)
        #pragma unroll
        for (int nb = 0; nb < 4; ++nb)
            #pragma unroll
            for (int r = 0; r < 4; ++r) acc[mt][nb][r] = 0.f;

    const int kIters = K / GM_BK;   // 16
    loadTile(0, 0);
    loadTile(1, 1);

    for (int it = 0; it < kIters; ++it) {
        if (it < kIters - 1)
            asm volatile("cp.async.wait_group 1;" ::: "memory");
        else
            asm volatile("cp.async.wait_group 0;" ::: "memory");
        __syncthreads();

        const uint32_t sa = sBase + (it & 1) * G1_STG_BYTES;
        const uint32_t sb = sa + 16384;

        #pragma unroll
        for (int k16 = 0; k16 < 4; ++k16) {
            uint32_t af[4][4];
            #pragma unroll
            for (int mt = 0; mt < 4; ++mt)
                ldm_x4(af[mt][0], af[mt][1], af[mt][2], af[mt][3],
                       sa + 2 * sw_off(wm + mt * 16 + lrow, k16 * 16 + lcol8));
            uint32_t bfr[4][2];
            #pragma unroll
            for (int nt = 0; nt < 2; ++nt) {
                uint32_t r0, r1, r2, r3;
                ldm_x4(r0, r1, r2, r3,
                       sb + 2 * sw_off(wn + nt * 16 + lrow, k16 * 16 + lcol8));
                bfr[2 * nt][0] = r0; bfr[2 * nt][1] = r2;
                bfr[2 * nt + 1][0] = r1; bfr[2 * nt + 1][1] = r3;
            }
            #pragma unroll
            for (int mt = 0; mt < 4; ++mt)
                #pragma unroll
                for (int nb = 0; nb < 4; ++nb)
                    mma16816_f16(acc[mt][nb], af[mt], bfr[nb][0], bfr[nb][1]);
        }

        __syncthreads();
        if (it + 2 < kIters) loadTile(it + 2, it & 1);
        else asm volatile("cp.async.commit_group;" ::: "memory");
    }

    // ---- fused epilogue ----
    const int sec = n0 >> 10;               // 0=q, 1=k, 2=v
    const int h   = (n0 & 1023) >> 6;
    const int b   = m0 >> 11;
    const int t0  = m0 & (SEQ - 1);
    __half* outbase = (sec == 0 ? qb : (sec == 1 ? kb : vb))
                      + ((size_t)(b * NHEAD + h) * SEQ + t0) * HDIM;

    if (sec == 2) {
        #pragma unroll
        for (int mt = 0; mt < 4; ++mt) {
            const int r0 = wm + mt * 16 + (lane >> 2);
            #pragma unroll
            for (int nb = 0; nb < 4; ++nb) {
                const int cidx = wn + nb * 8 + (lane & 3) * 2;
                const float b0 = bias[n0 + cidx], b1 = bias[n0 + cidx + 1];
                *(__half2*)(outbase + (size_t)r0 * HDIM + cidx) =
                    __floats2half2_rn(acc[mt][nb][0] + b0, acc[mt][nb][1] + b1);
                *(__half2*)(outbase + (size_t)(r0 + 8) * HDIM + cidx) =
                    __floats2half2_rn(acc[mt][nb][2] + b0, acc[mt][nb][3] + b1);
            }
        }
        return;
    }

    // q/k: stage fp32 acc+bias in smem (32 KB, fits in the 48 KB pipeline
    // buffers), then RoPE rotate (fp32) + fp16 store.
    float* st = (float*)smem_dyn;
    __syncthreads();                // all warps done with pipeline smem
    #pragma unroll
    for (int mt = 0; mt < 4; ++mt) {
        const int r0 = wm + mt * 16 + (lane >> 2);
        #pragma unroll
        for (int nb = 0; nb < 4; ++nb) {
            const int cidx = wn + nb * 8 + (lane & 3) * 2;
            const float b0 = bias[n0 + cidx], b1 = bias[n0 + cidx + 1];
            st[r0 * 64 + cidx]           = acc[mt][nb][0] + b0;
            st[r0 * 64 + cidx + 1]       = acc[mt][nb][1] + b1;
            st[(r0 + 8) * 64 + cidx]     = acc[mt][nb][2] + b0;
            st[(r0 + 8) * 64 + cidx + 1] = acc[mt][nb][3] + b1;
        }
    }
    __syncthreads();

    const float QS = (sec == 0) ? 0.125f * 1.4426950408889634f : 1.0f;
    #pragma unroll
    for (int i = 0; i < 16; ++i) {
        const int row = i * 8 + (tid >> 4);
        const int d   = (tid & 15) * 2;
        const float x1a = st[row * 64 + d];
        const float x1b = st[row * 64 + d + 1];
        const float x2a = st[row * 64 + d + 32];
        const float x2b = st[row * 64 + d + 33];

        const float tf = (float)(t0 + row);
        float sa, ca, sb_, cb;
        const float fa = exp2f((float)d       * (-13.2877123795494493f / 32.0f));
        const float fb = exp2f((float)(d + 1) * (-13.2877123795494493f / 32.0f));
        sincosf(tf * fa, &sa, &ca);
        sincosf(tf * fb, &sb_, &cb);

        const float o1a = (x1a * ca - x2a * sa) * QS;
        const float o1b = (x1b * cb - x2b * sb_) * QS;
        const float o2a = (x2a * ca + x1a * sa) * QS;
        const float o2b = (x2b * cb + x1b * sb_) * QS;

        *(__half2*)(outbase + (size_t)row * HDIM + d)      = __floats2half2_rn(o1a, o1b);
        *(__half2*)(outbase + (size_t)row * HDIM + d + 32) = __floats2half2_rn(o2a, o2b);
    }
}

// ---------------------------------------------------------------------------
// GEMM2 (R14 best): fp16 in, fp32 out, 128x128x64, 3-stage, 256 threads.
// ---------------------------------------------------------------------------
#define GM_NSTG 3
#define GM_STG_BYTES 32768   // 16KB A + 16KB B

__global__ __launch_bounds__(256) void hgemm_bias_kernel(
    const __half* __restrict__ A,   // [M][K]
    const __half* __restrict__ Bt,  // [N][K]
    const float* __restrict__ bias, float* __restrict__ C,
    int M, int N, int K)
{
    const int tid = threadIdx.x, lane = tid & 31, wid = tid >> 5;
    const int m0 = blockIdx.y * 128, n0 = blockIdx.x * 128;
    const int wm = (wid >> 2) * 64, wn = (wid & 3) * 32;
    const int lrow = lane & 15, lcol8 = (lane >> 4) * 8;

    const uint32_t sBase = (uint32_t)__cvta_generic_to_shared(smem_dyn);

    const __half* Ag = A  + (size_t)m0 * K;
    const __half* Bg = Bt + (size_t)n0 * K;

    auto loadTile = [&](int it, int stg) {
        const __half* ag = Ag + it * GM_BK;
        const __half* bg = Bg + it * GM_BK;
        const uint32_t sa = sBase + stg * GM_STG_BYTES;
        const uint32_t sb = sa + 16384;
        #pragma unroll
        for (int e = tid; e < 1024; e += 256) {
            const int row = e >> 3, ch = e & 7;
            const uint32_t so = 2 * sw_off(row, ch * 8);
            cp16(sa + so, ag + (size_t)row * K + ch * 8);
            cp16(sb + so, bg + (size_t)row * K + ch * 8);
        }
        asm volatile("cp.async.commit_group;" ::: "memory");
    };

    float acc[4][4][4];
    #pragma unroll
    for (int mt = 0; mt < 4; ++mt)
        #pragma unroll
        for (int nb = 0; nb < 4; ++nb)
            #pragma unroll
            for (int r = 0; r < 4; ++r) acc[mt][nb][r] = 0.f;

    const int kIters = K / GM_BK;
    loadTile(0, 0);
    loadTile(1, 1);

    for (int it = 0; it < kIters; ++it) {
        asm volatile("cp.async.wait_group 1;" ::: "memory");
        __syncthreads();

        if (it + 2 < kIters) loadTile(it + 2, (it + 2) % GM_NSTG);
        else asm volatile("cp.async.commit_group;" ::: "memory");

        const uint32_t sa = sBase + (it % GM_NSTG) * GM_STG_BYTES;
        const uint32_t sb = sa + 16384;

        #pragma unroll
        for (int k16 = 0; k16 < 4; ++k16) {
            uint32_t af[4][4];
            #pragma unroll
            for (int mt = 0; mt < 4; ++mt)
                ldm_x4(af[mt][0], af[mt][1], af[mt][2], af[mt][3],
                       sa + 2 * sw_off(wm + mt * 16 + lrow, k16 * 16 + lcol8));
            uint32_t bfr[4][2];
            #pragma unroll
            for (int nt = 0; nt < 2; ++nt) {
                uint32_t r0, r1, r2, r3;
                ldm_x4(r0, r1, r2, r3,
                       sb + 2 * sw_off(wn + nt * 16 + lrow, k16 * 16 + lcol8));
                bfr[2 * nt][0] = r0; bfr[2 * nt][1] = r2;
                bfr[2 * nt + 1][0] = r1; bfr[2 * nt + 1][1] = r3;
            }
            #pragma unroll
            for (int mt = 0; mt < 4; ++mt)
                #pragma unroll
                for (int nb = 0; nb < 4; ++nb)
                    mma16816_f16(acc[mt][nb], af[mt], bfr[nb][0], bfr[nb][1]);
        }
    }

    #pragma unroll
    for (int mt = 0; mt < 4; ++mt) {
        const int r0 = m0 + wm + mt * 16 + (lane >> 2);
        #pragma unroll
        for (int nb = 0; nb < 4; ++nb) {
            const int cidx = n0 + wn + nb * 8 + (lane & 3) * 2;
            const float b0 = bias[cidx], b1 = bias[cidx + 1];
            *(float2*)(C + (size_t)r0 * N + cidx) =
                make_float2(acc[mt][nb][0] + b0, acc[mt][nb][1] + b1);
            *(float2*)(C + (size_t)(r0 + 8) * N + cidx) =
                make_float2(acc[mt][nb][2] + b0, acc[mt][nb][3] + b1);
        }
    }
}

// ---------------------------------------------------------------------------
// fp16 flash attention — FA_BM=64, 128 threads, 4 CTAs/SM (unchanged R14).
// ---------------------------------------------------------------------------
#define FA_BM 64
#define FA_BN 64
#define FA_TILES (SEQ / FA_BN)   // 32

__global__ __launch_bounds__(128, 4) void fa_kernel(
    const __half* __restrict__ Q, const __half* __restrict__ K,
    const __half* __restrict__ V, __half* __restrict__ attn)
{
    const int bh = blockIdx.y;
    const int b  = bh >> 4;
    const int h  = bh & 15;
    const int q0 = blockIdx.x * FA_BM;
    const int tid  = threadIdx.x;
    const int lane = tid & 31;
    const int wid  = tid >> 5;

    __shared__ __half sQ[FA_BM * HDIM];           // 8 KB
    __shared__ __half sK[2][FA_BN * HDIM];        // 16 KB
    __shared__ __half sV[2][FA_BN * HDIM];        // 16 KB

    const __half* qg = Q + ((size_t)bh * SEQ + q0) * HDIM;
    const __half* kg = K + (size_t)bh * SEQ * HDIM;
    const __half* vg = V + (size_t)bh * SEQ * HDIM;

    const uint32_t sQb  = (uint32_t)__cvta_generic_to_shared(sQ);
    const uint32_t sKb0 = (uint32_t)__cvta_generic_to_shared(sK[0]);
    const uint32_t sKb1 = (uint32_t)__cvta_generic_to_shared(sK[1]);
    const uint32_t sVb0 = (uint32_t)__cvta_generic_to_shared(sV[0]);
    const uint32_t sVb1 = (uint32_t)__cvta_generic_to_shared(sV[1]);

    #pragma unroll
    for (int e = tid; e < FA_BM * 8; e += 128) {
        const int row = e >> 3, ch = e & 7;
        *(uint4*)&sQ[sw_off(row, ch * 8)] = *(const uint4*)(qg + row * 64 + ch * 8);
    }

    #pragma unroll
    for (int pt = 0; pt < 2; ++pt) {
        const __half* kt = kg + pt * FA_BN * HDIM;
        const __half* vt = vg + pt * FA_BN * HDIM;
        const uint32_t kb = pt ? sKb1 : sKb0;
        const uint32_t vb = pt ? sVb1 : sVb0;
        #pragma unroll
        for (int e = tid; e < FA_BN * 8; e += 128) {
            const int row = e >> 3, ch = e & 7;
            const uint32_t so = 2 * sw_off(row, ch * 8);
            cp16(kb + so, kt + row * 64 + ch * 8);
            cp16(vb + so, vt + row * 64 + ch * 8);
        }
        asm volatile("cp.async.commit_group;" ::: "memory");
    }

    __syncthreads();

    uint32_t aq[4][4];
    {
        const int qr = wid * 16 + (lane & 15);
        const int qc = (lane >> 4) * 8;
        #pragma unroll
        for (int c4 = 0; c4 < 4; ++c4)
            ldm_x4(aq[c4][0], aq[c4][1], aq[c4][2], aq[c4][3],
                   sQb + 2 * sw_off(qr, c4 * 16 + qc));
    }

    float o[8][4];
    #pragma unroll
    for (int j = 0; j < 8; ++j)
        #pragma unroll
        for (int r = 0; r < 4; ++r) o[j][r] = 0.f;
    float m0 = -1e30f, m1 = -1e30f, l0 = 0.f, l1 = 0.f;

    const int lrow = lane & 15;
    const int lcol8 = (lane >> 4) * 8;

    for (int t = 0; t < FA_TILES; ++t) {
        if (t < FA_TILES - 1)
            asm volatile("cp.async.wait_group 1;" ::: "memory");
        else
            asm volatile("cp.async.wait_group 0;" ::: "memory");
        __syncthreads();

        const uint32_t kb = (t & 1) ? sKb1 : sKb0;
        const uint32_t vb = (t & 1) ? sVb1 : sVb0;

        float c[8][4];
        #pragma unroll
        for (int j = 0; j < 8; ++j)
            #pragma unroll
            for (int r = 0; r < 4; ++r) c[j][r] = 0.f;

        #pragma unroll
        for (int n16 = 0; n16 < 4; ++n16) {
            #pragma unroll
            for (int dc = 0; dc < 4; ++dc) {
                uint32_t r0, r1, r2, r3;
                ldm_x4(r0, r1, r2, r3,
                       kb + 2 * sw_off(n16 * 16 + lrow, dc * 16 + lcol8));
                mma16816_f16(c[2 * n16 + 0], aq[dc], r0, r2);
                mma16816_f16(c[2 * n16 + 1], aq[dc], r1, r3);
            }
        }

        float t0 = -1e30f, t1 = -1e30f;
        #pragma unroll
        for (int j = 0; j < 8; ++j) {
            t0 = fmaxf(t0, fmaxf(c[j][0], c[j][1]));
            t1 = fmaxf(t1, fmaxf(c[j][2], c[j][3]));
        }
        t0 = fmaxf(t0, __shfl_xor_sync(0xffffffffu, t0, 1));
        t0 = fmaxf(t0, __shfl_xor_sync(0xffffffffu, t0, 2));
        t1 = fmaxf(t1, __shfl_xor_sync(0xffffffffu, t1, 1));
        t1 = fmaxf(t1, __shfl_xor_sync(0xffffffffu, t1, 2));

        const float m0n = fmaxf(m0, t0);
        const float m1n = fmaxf(m1, t1);
        const float a0 = ex2f(m0 - m0n);
        const float a1 = ex2f(m1 - m1n);
        m0 = m0n; m1 = m1n;

        #pragma unroll
        for (int j = 0; j < 8; ++j) {
            o[j][0] *= a0; o[j][1] *= a0;
            o[j][2] *= a1; o[j][3] *= a1;
        }

        float s0 = 0.f, s1 = 0.f;
        #pragma unroll
        for (int kc = 0; kc < 4; ++kc) {
            uint32_t ap[4];
            #pragma unroll
            for (int jj = 0; jj < 2; ++jj) {
                const int j = 2 * kc + jj;
                const float p0 = ex2f(c[j][0] - m0);
                const float p1 = ex2f(c[j][1] - m0);
                const float p2 = ex2f(c[j][2] - m1);
                const float p3 = ex2f(c[j][3] - m1);
                s0 += p0 + p1;
                s1 += p2 + p3;
                __half2 u = __floats2half2_rn(p0, p1);
                __half2 w = __floats2half2_rn(p2, p3);
                ap[2 * jj + 0] = *(uint32_t*)&u;
                ap[2 * jj + 1] = *(uint32_t*)&w;
            }
            #pragma unroll
            for (int dc = 0; dc < 4; ++dc) {
                uint32_t r0, r1, r2, r3;
                ldm_x4_t(r0, r1, r2, r3,
                         vb + 2 * sw_off(kc * 16 + lrow, dc * 16 + lcol8));
                mma16816_f16(o[2 * dc + 0], ap, r0, r1);
                mma16816_f16(o[2 * dc + 1], ap, r2, r3);
            }
        }

        s0 += __shfl_xor_sync(0xffffffffu, s0, 1);
        s0 += __shfl_xor_sync(0xffffffffu, s0, 2);
        s1 += __shfl_xor_sync(0xffffffffu, s1, 1);
        s1 += __shfl_xor_sync(0xffffffffu, s1, 2);
        l0 = l0 * a0 + s0;
        l1 = l1 * a1 + s1;

        __syncthreads();

        if (t + 2 < FA_TILES) {
            const __half* kt = kg + (t + 2) * FA_BN * HDIM;
            const __half* vt = vg + (t + 2) * FA_BN * HDIM;
            const uint32_t kbn = (t & 1) ? sKb1 : sKb0;
            const uint32_t vbn = (t & 1) ? sVb1 : sVb0;
            #pragma unroll
            for (int e = tid; e < FA_BN * 8; e += 128) {
                const int row = e >> 3, ch = e & 7;
                const uint32_t so = 2 * sw_off(row, ch * 8);
                cp16(kbn + so, kt + row * 64 + ch * 8);
                cp16(vbn + so, vt + row * 64 + ch * 8);
            }
        }
        asm volatile("cp.async.commit_group;" ::: "memory");
    }

    const float inv0 = 1.0f / l0;
    const float inv1 = 1.0f / l1;
    const int g = lane >> 2;
    const int cq = (lane & 3) * 2;
    const int row0 = q0 + wid * 16 + g;
    const int row1 = row0 + 8;
    __half* ab0 = attn + (size_t)(b * SEQ + row0) * CDIM + h * HDIM + cq;
    __half* ab1 = attn + (size_t)(b * SEQ + row1) * CDIM + h * HDIM + cq;
    #pragma unroll
    for (int j = 0; j < 8; ++j) {
        *(__half2*)(ab0 + j * 8) = __floats2half2_rn(o[j][0] * inv0, o[j][1] * inv0);
        *(__half2*)(ab1 + j * 8) = __floats2half2_rn(o[j][2] * inv1, o[j][3] * inv1);
    }
}

// ---------------------------------------------------------------------------
// Launch
// ---------------------------------------------------------------------------
extern "C" void kernel_launch(void* const* d_in, const int* in_sizes, int n_in,
                              void* d_out, int out_size)
{
    const float* x    = (const float*)d_in[0];
    const float* Wqkv = (const float*)d_in[1];
    const float* bqkv = (const float*)d_in[2];
    const float* Wout = (const float*)d_in[3];
    const float* bout = (const float*)d_in[4];
    float* out = (float*)d_out;

    __half *x16 = nullptr, *qb = nullptr, *kb = nullptr, *vb = nullptr;
    __half *attn = nullptr, *W1 = nullptr, *W2 = nullptr;
    cudaGetSymbolAddress((void**)&x16, g_x16);
    cudaGetSymbolAddress((void**)&qb, g_qb);
    cudaGetSymbolAddress((void**)&kb, g_kb);
    cudaGetSymbolAddress((void**)&vb, g_vb);
    cudaGetSymbolAddress((void**)&attn, g_attn);
    cudaGetSymbolAddress((void**)&W1,  g_W1);
    cudaGetSymbolAddress((void**)&W2,  g_W2);

    const int G1_SMEM = G1_NSTG * G1_STG_BYTES;     // 49152
    const int G2_SMEM = GM_NSTG * GM_STG_BYTES;     // 98304
    cudaFuncSetAttribute(hgemm_rope_kernel,
                         cudaFuncAttributeMaxDynamicSharedMemorySize, G1_SMEM);
    cudaFuncSetAttribute(hgemm_bias_kernel,
                         cudaFuncAttributeMaxDynamicSharedMemorySize, G2_SMEM);

    // 1) fused prep: cast x -> x16, transpose Wqkv -> W1, Wout -> W2
    prep_kernel<<<PREP_CAST_BLKS + PREP_W1_BLKS + PREP_W2_BLKS, 256>>>(
        x, x16, Wqkv, W1, Wout, W2);

    // 2) qkv GEMM + fused RoPE + relayout -> qb/kb/vb (2-stage, 4 CTA/SM)
    hgemm_rope_kernel<<<dim3(QKVC / 64, MROWS / 128), 128, G1_SMEM>>>(
        x16, W1, bqkv, qb, kb, vb, MROWS, QKVC, CDIM);

    // 3) flash attention -> attn fp16
    fa_kernel<<<dim3(SEQ / FA_BM, BATCH * NHEAD), 128>>>(qb, kb, vb, attn);

    // 4) out = attn @ Wout + bout
    hgemm_bias_kernel<<<dim3(CDIM / 128, MROWS / 128), 256, G2_SMEM>>>(
        attn, W2, bout, out, MROWS, CDIM, CDIM);
}